// round 9
// baseline (speedup 1.0000x reference)
#include <cuda_runtime.h>
#include <math.h>
#include <stdint.h>

#define B_    256
#define G_    16
#define GS_   588
#define GSP   640
#define HID_  1024
#define FEAT_ 2048
#define NSPL  32
#define KSPL  1024
#define NSPL4 8
#define KSPL4 128

#define THREADS 512
#define BM 64
#define BN 128
#define BK 64
#define ASTR 80

#define PB_A1 0
#define PB_A0 5120
#define PB_B1 10240
#define PB_B0 20480
#define BUF_BYTES 30720
#define SMEM_TOTAL (2 * BUF_BYTES)

#define QMAX 16256.0f

#define OFF_W1Q 0
#define OFF_W1K 16384
#define OFF_W4Q 32768
#define OFF_W4K 65536
#define OFF_G1  98304
#define OFF_G4  99328
#define N_SC    101376

// ---------------- scratch ----------------
__device__ __align__(128) int8_t qL1[(size_t)2 * B_ * G_ * GSP];
__device__ __align__(128) int8_t qL0[(size_t)2 * B_ * G_ * GSP];
__device__ float  sa_qk[2 * B_ * G_];
__device__ float  g_h[(size_t)2 * B_ * G_ * HID_];
__device__ __align__(128) int8_t hL1[(size_t)2 * B_ * G_ * HID_];
__device__ __align__(128) int8_t hL0[(size_t)2 * B_ * G_ * HID_];
__device__ float  sa_h[2 * B_ * G_];
__device__ float  g_f[(size_t)2 * B_ * G_ * FEAT_];
__device__ __align__(128) int8_t fL1[(size_t)2 * B_ * G_ * FEAT_];
__device__ __align__(128) int8_t fL0[(size_t)2 * B_ * G_ * FEAT_];
__device__ float  sa_f[2 * B_ * NSPL];
__device__ float  g_part[(size_t)NSPL * 2 * B_ * HID_];
__device__ __align__(128) int8_t hgL1[(size_t)2 * B_ * HID_];
__device__ __align__(128) int8_t hgL0[(size_t)2 * B_ * HID_];
__device__ float  sa_hg[2 * B_ * NSPL4];
__device__ float  g_part4[(size_t)NSPL4 * 2 * B_ * FEAT_];
__device__ float  g_o[(size_t)2 * B_ * FEAT_];
__device__ float  g_scores[B_];
__device__ unsigned int u_cmax[N_SC];
__device__ float  s_w[N_SC];
__device__ float  inv_w[N_SC];

__device__ __forceinline__ float silu_f(float v) { return v / (1.0f + __expf(-v)); }
__device__ __forceinline__ uint32_t smem_to_u32(const void* p) {
    uint32_t a;
    asm("{ .reg .u64 t; cvta.to.shared.u64 t, %1; cvt.u32.u64 %0, t; }" : "=r"(a) : "l"(p));
    return a;
}
__device__ __forceinline__ uint32_t lds32(uint32_t a) {
    uint32_t v; asm volatile("ld.shared.b32 %0, [%1];" : "=r"(v) : "r"(a)); return v;
}
__device__ __forceinline__ void sts32(uint32_t a, uint32_t v) {
    asm volatile("st.shared.b32 [%0], %1;" :: "r"(a), "r"(v));
}
__device__ __forceinline__ void mma_s8(int* d, const uint32_t* a, const uint32_t* b) {
    asm volatile(
        "mma.sync.aligned.m16n8k32.row.col.s32.s8.s8.s32 "
        "{%0,%1,%2,%3}, {%4,%5,%6,%7}, {%8,%9}, {%0,%1,%2,%3};"
        : "+r"(d[0]), "+r"(d[1]), "+r"(d[2]), "+r"(d[3])
        : "r"(a[0]), "r"(a[1]), "r"(a[2]), "r"(a[3]), "r"(b[0]), "r"(b[1]));
}
__device__ __forceinline__ void cp_async16(uint32_t dst, const void* src) {
    asm volatile("cp.async.ca.shared.global [%0], [%1], 16;" :: "r"(dst), "l"(src));
}
__device__ __forceinline__ void cp_async_commit() { asm volatile("cp.async.commit_group;" ::: "memory"); }
__device__ __forceinline__ void cp_async_wait0()  { asm volatile("cp.async.wait_group 0;" ::: "memory"); }

template<int NTHR>
__device__ __forceinline__ float block_max(float v, float* sh, int tid) {
    sh[tid] = v; __syncthreads();
    #pragma unroll
    for (int o = NTHR / 2; o > 0; o >>= 1) {
        if (tid < o) sh[tid] = fmaxf(sh[tid], sh[tid + o]);
        __syncthreads();
    }
    float r = sh[0]; __syncthreads();
    return r;
}
__device__ __forceinline__ void quant_store(float x, float inv, int8_t* p1, int8_t* p0) {
    const int xi = __float2int_rn(x * inv);
    const int h = (xi + 64) >> 7;
    *p1 = (int8_t)h;
    *p0 = (int8_t)(xi - (h << 7));
}
__device__ __forceinline__ float comb(int hh, int xx) {
    return fmaf((float)hh, 16384.0f, (float)xx * 128.0f);
}

// ================= int8 GEMM body: BM=64 x BN=128 x BK=64, 512 thr =================
__device__ __forceinline__ void gemm_s8_body(
    const int8_t* __restrict__ A1, const int8_t* __restrict__ A0, int lda,
    const float* __restrict__ W, int ldw, int K,
    int m0, int n0, const float* __restrict__ invW,
    int acc_hh[2][2][4], int acc_x[2][2][4])
{
    extern __shared__ char dyn[];
    const uint32_t sb = smem_to_u32(dyn);
    const int tid = threadIdx.x, lane = tid & 31, wid = tid >> 5;
    const int wm = (wid >> 3) * 32;
    const int wn = (wid & 7) * 16;

    const int a_row = tid & 63;
    const int a_seg = (tid >> 6) & 3;
    const int a_limb = tid >> 8;
    const int8_t* Asrc = (a_limb ? A0 : A1) + (size_t)(m0 + a_row) * lda + a_seg * 16;
    const uint32_t a_dst = (a_limb ? PB_A0 : PB_A1) + (uint32_t)(a_row * ASTR + a_seg * 16);

    const int n_lo = tid & 7, k_lo = (tid >> 3) & 3;
    const int n_hi = (tid >> 5) & 3, k_hi = tid >> 7;
    const int ncol = (n_hi * 8 + n_lo) * 4;
    const int krow = (k_hi * 4 + k_lo) * 4;

    float invb[4];
    #pragma unroll
    for (int j = 0; j < 4; ++j) invb[j] = invW[n0 + ncol + j];

    #pragma unroll
    for (int mt = 0; mt < 2; ++mt)
        #pragma unroll
        for (int nt = 0; nt < 2; ++nt)
            #pragma unroll
            for (int e = 0; e < 4; ++e) { acc_hh[mt][nt][e] = 0; acc_x[mt][nt][e] = 0; }

    float rbw[16];
    const int nk = (K + BK - 1) / BK;

    auto cpA = [&](int k0, int buf) {
        cp_async16(sb + buf * BUF_BYTES + a_dst, Asrc + k0);
    };
    auto ldgB = [&](int k0) {
        #pragma unroll
        for (int i = 0; i < 4; ++i) {
            const int r = k0 + krow + i;
            if (r < K) {
                float4 v = *reinterpret_cast<const float4*>(W + (size_t)r * ldw + n0 + ncol);
                rbw[i*4+0] = v.x; rbw[i*4+1] = v.y; rbw[i*4+2] = v.z; rbw[i*4+3] = v.w;
            } else {
                rbw[i*4+0] = 0.f; rbw[i*4+1] = 0.f; rbw[i*4+2] = 0.f; rbw[i*4+3] = 0.f;
            }
        }
    };
    auto stB = [&](int buf) {
        const uint32_t base = sb + buf * BUF_BYTES;
        #pragma unroll
        for (int j = 0; j < 4; ++j) {
            uint32_t w1 = 0, w0 = 0;
            #pragma unroll
            for (int i = 0; i < 4; ++i) {
                const int xi = __float2int_rn(rbw[i*4+j] * invb[j]);
                const int h = (xi + 64) >> 7;
                const int l = xi - (h << 7);
                w1 |= (uint32_t)(h & 0xff) << (8 * i);
                w0 |= (uint32_t)(l & 0xff) << (8 * i);
            }
            const uint32_t off = (uint32_t)((ncol + j) * ASTR + krow);
            sts32(base + PB_B1 + off, w1);
            sts32(base + PB_B0 + off, w0);
        }
    };

    cpA(0, 0);
    ldgB(0);
    stB(0);
    cp_async_commit();
    cp_async_wait0();
    __syncthreads();

    const int g4 = (lane >> 2) * ASTR;
    const int t4 = (lane & 3) * 4;

    for (int t = 0; t < nk; ++t) {
        const int cur = t & 1, nxt = (t + 1) & 1;
        const bool more = (t + 1) < nk;

        if (more) {
            cpA((t + 1) * BK, nxt);
            cp_async_commit();
            ldgB((t + 1) * BK);
        }
        {
            const uint32_t a1B = sb + cur * BUF_BYTES + PB_A1;
            const uint32_t a0B = sb + cur * BUF_BYTES + PB_A0;
            const uint32_t b1B = sb + cur * BUF_BYTES + PB_B1;
            const uint32_t b0B = sb + cur * BUF_BYTES + PB_B0;
            #pragma unroll
            for (int ks = 0; ks < 2; ++ks) {
                const int kb = ks * 32 + t4;
                uint32_t ah[2][4], al[2][4], bh[2][2], bl[2][2];
                #pragma unroll
                for (int mt = 0; mt < 2; ++mt) {
                    const uint32_t ro = (uint32_t)((wm + mt * 16) * ASTR) + g4 + kb;
                    ah[mt][0] = lds32(a1B + ro);
                    ah[mt][1] = lds32(a1B + ro + 8 * ASTR);
                    ah[mt][2] = lds32(a1B + ro + 16);
                    ah[mt][3] = lds32(a1B + ro + 8 * ASTR + 16);
                    al[mt][0] = lds32(a0B + ro);
                    al[mt][1] = lds32(a0B + ro + 8 * ASTR);
                    al[mt][2] = lds32(a0B + ro + 16);
                    al[mt][3] = lds32(a0B + ro + 8 * ASTR + 16);
                }
                #pragma unroll
                for (int nt = 0; nt < 2; ++nt) {
                    const uint32_t no = (uint32_t)((wn + nt * 8) * ASTR) + g4 + kb;
                    bh[nt][0] = lds32(b1B + no);
                    bh[nt][1] = lds32(b1B + no + 16);
                    bl[nt][0] = lds32(b0B + no);
                    bl[nt][1] = lds32(b0B + no + 16);
                }
                #pragma unroll
                for (int mt = 0; mt < 2; ++mt)
                    #pragma unroll
                    for (int nt = 0; nt < 2; ++nt)
                        mma_s8(acc_hh[mt][nt], ah[mt], bh[nt]);
                #pragma unroll
                for (int mt = 0; mt < 2; ++mt)
                    #pragma unroll
                    for (int nt = 0; nt < 2; ++nt)
                        mma_s8(acc_x[mt][nt], ah[mt], bl[nt]);
                #pragma unroll
                for (int mt = 0; mt < 2; ++mt)
                    #pragma unroll
                    for (int nt = 0; nt < 2; ++nt)
                        mma_s8(acc_x[mt][nt], al[mt], bh[nt]);
            }
        }
        if (more) {
            stB(nxt);
            cp_async_wait0();
        }
        __syncthreads();
    }
}

// ================= pre-pass kernels =================
__global__ void __launch_bounds__(256) k_zero_cmax() {
    const int i = blockIdx.x * 256 + threadIdx.x;
    if (i < N_SC) u_cmax[i] = 0u;
}

__global__ void __launch_bounds__(256) k_colmax(
    const float* __restrict__ W, int K, int C, int R, int out_off)
{
    const int col = blockIdx.y * 256 + threadIdx.x;
    if (col >= C) return;
    int r = blockIdx.x * 256;
    const int rend = min(r + 256, R);
    int g = r / K;
    int nxt = (g + 1) * K;
    float mx = 0.f;
    for (; r < rend; ++r) {
        if (r == nxt) {
            if (mx > 0.f) atomicMax(&u_cmax[out_off + g * C + col], __float_as_uint(mx));
            mx = 0.f; ++g; nxt += K;
        }
        mx = fmaxf(mx, fabsf(W[(size_t)r * C + col]));
    }
    if (mx > 0.f) atomicMax(&u_cmax[out_off + g * C + col], __float_as_uint(mx));
}

__global__ void __launch_bounds__(256) k_finalize_scales() {
    const int i = blockIdx.x * 256 + threadIdx.x;
    if (i >= N_SC) return;
    const float m = __uint_as_float(u_cmax[i]);
    s_w[i] = m * (1.0f / QMAX);
    inv_w[i] = (m > 0.f) ? (QMAX / m) : 0.f;
}

__global__ void __launch_bounds__(128) k_quant_qk(
    const float* __restrict__ q, const float* __restrict__ k)
{
    __shared__ float sh[128];
    const int g = blockIdx.x, b = blockIdx.y, br = blockIdx.z;
    const int tid = threadIdx.x;
    const float* src = (br ? k : q) + (size_t)b * (G_ * GS_) + g * GS_;
    float mx = 0.f;
    for (int i = tid; i < GS_; i += 128) mx = fmaxf(mx, fabsf(src[i]));
    mx = block_max<128>(mx, sh, tid);
    const float inv = (mx > 0.f) ? (QMAX / mx) : 0.f;
    if (tid == 0) sa_qk[(br * B_ + b) * G_ + g] = mx * (1.0f / QMAX);
    const size_t base = ((size_t)(br * B_ + b) * G_ + g) * GSP;
    for (int i = tid; i < GSP; i += 128) {
        const float x = (i < GS_) ? src[i] : 0.f;
        quant_store(x, inv, &qL1[base + i], &qL0[base + i]);
    }
}

__global__ void __launch_bounds__(256) k_quant_h() {
    __shared__ float sh[256];
    const int g = blockIdx.x, row = blockIdx.y;
    const int tid = threadIdx.x;
    const float* src = g_h + (size_t)row * (G_ * HID_) + g * HID_;
    float mx = 0.f;
    for (int i = tid; i < HID_; i += 256) mx = fmaxf(mx, fabsf(src[i]));
    mx = block_max<256>(mx, sh, tid);
    const float inv = (mx > 0.f) ? (QMAX / mx) : 0.f;
    if (tid == 0) sa_h[row * G_ + g] = mx * (1.0f / QMAX);
    const size_t base = ((size_t)row * G_ + g) * HID_;
    for (int i = tid; i < HID_; i += 256)
        quant_store(src[i], inv, &hL1[base + i], &hL0[base + i]);
}

__global__ void __launch_bounds__(256) k_quant_f() {
    __shared__ float sh[256];
    const int s = blockIdx.x, row = blockIdx.y;
    const int tid = threadIdx.x;
    const size_t base = (size_t)row * (G_ * FEAT_) + (size_t)s * KSPL;
    float mx = 0.f;
    for (int i = tid; i < KSPL; i += 256) mx = fmaxf(mx, fabsf(g_f[base + i]));
    mx = block_max<256>(mx, sh, tid);
    const float inv = (mx > 0.f) ? (QMAX / mx) : 0.f;
    if (tid == 0) sa_f[row * NSPL + s] = mx * (1.0f / QMAX);
    for (int i = tid; i < KSPL; i += 256)
        quant_store(g_f[base + i], inv, &fL1[base + i], &fL0[base + i]);
}

// ================= GEMM stage kernels =================
__global__ void __launch_bounds__(THREADS, 1) k_fc1g(
    const float* __restrict__ Wq1, const float* __restrict__ bq1,
    const float* __restrict__ Wk1, const float* __restrict__ bk1)
{
    const int z = blockIdx.z, br = z >> 4, g = z & 15;
    const int m0 = blockIdx.x * BM, n0 = blockIdx.y * BN;

    const size_t abase = ((size_t)(br * B_) * G_ + g) * GSP;
    const float* W = (br ? Wk1 : Wq1) + (size_t)g * GS_ * HID_;
    const float* bias = (br ? bk1 : bq1) + g * HID_;
    const float* invW = inv_w + (br ? OFF_W1K : OFF_W1Q) + g * HID_;
    const float* sW = s_w + (br ? OFF_W1K : OFF_W1Q) + g * HID_;

    int hh[2][2][4], xx[2][2][4];
    gemm_s8_body(qL1 + abase, qL0 + abase, G_ * GSP, W, HID_, GS_, m0, n0, invW, hh, xx);

    const int lane = threadIdx.x & 31, wid = threadIdx.x >> 5;
    const int wm = (wid >> 3) * 32, wn = (wid & 7) * 16;
    #pragma unroll
    for (int mt = 0; mt < 2; ++mt) {
        const int r = m0 + wm + mt * 16 + (lane >> 2);
        const float sa0 = sa_qk[(br * B_ + r) * G_ + g];
        const float sa1 = sa_qk[(br * B_ + r + 8) * G_ + g];
        float* C0 = g_h + (size_t)(br * B_ + r) * (G_ * HID_) + g * HID_;
        float* C1 = g_h + (size_t)(br * B_ + r + 8) * (G_ * HID_) + g * HID_;
        #pragma unroll
        for (int nt = 0; nt < 2; ++nt) {
            const int c = n0 + wn + nt * 8 + (lane & 3) * 2;
            const float w0 = sW[c], w1 = sW[c + 1];
            C0[c]     = silu_f(comb(hh[mt][nt][0], xx[mt][nt][0]) * sa0 * w0 + bias[c]);
            C0[c + 1] = silu_f(comb(hh[mt][nt][1], xx[mt][nt][1]) * sa0 * w1 + bias[c + 1]);
            C1[c]     = silu_f(comb(hh[mt][nt][2], xx[mt][nt][2]) * sa1 * w0 + bias[c]);
            C1[c + 1] = silu_f(comb(hh[mt][nt][3], xx[mt][nt][3]) * sa1 * w1 + bias[c + 1]);
        }
    }
}

__global__ void __launch_bounds__(THREADS, 1) k_fc4g(
    const float* __restrict__ Wq4, const float* __restrict__ bq4,
    const float* __restrict__ Wk4, const float* __restrict__ bk4)
{
    const int z = blockIdx.z, br = z >> 4, g = z & 15;
    const int m0 = blockIdx.x * BM, n0 = blockIdx.y * BN;

    const size_t abase = ((size_t)(br * B_) * G_ + g) * HID_;
    const float* W = (br ? Wk4 : Wq4) + (size_t)g * HID_ * FEAT_;
    const float* bias = (br ? bk4 : bq4) + g * FEAT_;
    const float* invW = inv_w + (br ? OFF_W4K : OFF_W4Q) + g * FEAT_;
    const float* sW = s_w + (br ? OFF_W4K : OFF_W4Q) + g * FEAT_;

    int hh[2][2][4], xx[2][2][4];
    gemm_s8_body(hL1 + abase, hL0 + abase, G_ * HID_, W, FEAT_, HID_, m0, n0, invW, hh, xx);

    const int lane = threadIdx.x & 31, wid = threadIdx.x >> 5;
    const int wm = (wid >> 3) * 32, wn = (wid & 7) * 16;
    #pragma unroll
    for (int mt = 0; mt < 2; ++mt) {
        const int r = m0 + wm + mt * 16 + (lane >> 2);
        const float sa0 = sa_h[(br * B_ + r) * G_ + g];
        const float sa1 = sa_h[(br * B_ + r + 8) * G_ + g];
        float* C0 = g_f + (size_t)(br * B_ + r) * (G_ * FEAT_) + g;
        float* C1 = g_f + (size_t)(br * B_ + r + 8) * (G_ * FEAT_) + g;
        #pragma unroll
        for (int nt = 0; nt < 2; ++nt) {
            const int c = n0 + wn + nt * 8 + (lane & 3) * 2;
            const float w0 = sW[c], w1 = sW[c + 1];
            C0[(size_t)c * G_]       = silu_f(comb(hh[mt][nt][0], xx[mt][nt][0]) * sa0 * w0 + bias[c]);
            C0[(size_t)(c + 1) * G_] = silu_f(comb(hh[mt][nt][1], xx[mt][nt][1]) * sa0 * w1 + bias[c + 1]);
            C1[(size_t)c * G_]       = silu_f(comb(hh[mt][nt][2], xx[mt][nt][2]) * sa1 * w0 + bias[c]);
            C1[(size_t)(c + 1) * G_] = silu_f(comb(hh[mt][nt][3], xx[mt][nt][3]) * sa1 * w1 + bias[c + 1]);
        }
    }
}

__global__ void __launch_bounds__(THREADS, 1) k_gf1(const float* __restrict__ Wg1)
{
    const int s = blockIdx.z;
    const int m0 = blockIdx.x * BM, n0 = blockIdx.y * BN;

    const size_t abase = (size_t)s * KSPL;
    const float* W = Wg1 + (size_t)s * KSPL * HID_;

    int hh[2][2][4], xx[2][2][4];
    gemm_s8_body(fL1 + abase, fL0 + abase, G_ * FEAT_, W, HID_, KSPL,
                 m0, n0, inv_w + OFF_G1, hh, xx);

    const int lane = threadIdx.x & 31, wid = threadIdx.x >> 5;
    const int wm = (wid >> 3) * 32, wn = (wid & 7) * 16;
    const float* sW = s_w + OFF_G1;
    float* P = g_part + (size_t)s * (2 * B_ * HID_);
    #pragma unroll
    for (int mt = 0; mt < 2; ++mt) {
        const int r = m0 + wm + mt * 16 + (lane >> 2);
        const float sa0 = sa_f[r * NSPL + s];
        const float sa1 = sa_f[(r + 8) * NSPL + s];
        #pragma unroll
        for (int nt = 0; nt < 2; ++nt) {
            const int c = n0 + wn + nt * 8 + (lane & 3) * 2;
            P[(size_t)r * HID_ + c]           = comb(hh[mt][nt][0], xx[mt][nt][0]) * sa0 * sW[c];
            P[(size_t)r * HID_ + c + 1]       = comb(hh[mt][nt][1], xx[mt][nt][1]) * sa0 * sW[c + 1];
            P[(size_t)(r + 8) * HID_ + c]     = comb(hh[mt][nt][2], xx[mt][nt][2]) * sa1 * sW[c];
            P[(size_t)(r + 8) * HID_ + c + 1] = comb(hh[mt][nt][3], xx[mt][nt][3]) * sa1 * sW[c + 1];
        }
    }
}

__global__ void __launch_bounds__(128) k_reduce_silu_quant(const float* __restrict__ bg1)
{
    __shared__ float sh[128];
    const int chunk = blockIdx.x, row = blockIdx.y;
    const int tid = threadIdx.x;
    const int col = chunk * KSPL4 + tid;
    float v = bg1[col];
    #pragma unroll
    for (int s = 0; s < NSPL; ++s)
        v += g_part[(size_t)s * (2 * B_ * HID_) + (size_t)row * HID_ + col];
    v = silu_f(v);
    const float mx = block_max<128>(fabsf(v), sh, tid);
    const float inv = (mx > 0.f) ? (QMAX / mx) : 0.f;
    if (tid == 0) sa_hg[row * NSPL4 + chunk] = mx * (1.0f / QMAX);
    quant_store(v, inv, &hgL1[(size_t)row * HID_ + col], &hgL0[(size_t)row * HID_ + col]);
}

__global__ void __launch_bounds__(THREADS, 1) k_gf4(const float* __restrict__ Wg4)
{
    const int s = blockIdx.z;
    const int m0 = blockIdx.x * BM, n0 = blockIdx.y * BN;

    const size_t abase = (size_t)s * KSPL4;
    const float* W = Wg4 + (size_t)s * KSPL4 * FEAT_;

    int hh[2][2][4], xx[2][2][4];
    gemm_s8_body(hgL1 + abase, hgL0 + abase, HID_, W, FEAT_, KSPL4,
                 m0, n0, inv_w + OFF_G4, hh, xx);

    const int lane = threadIdx.x & 31, wid = threadIdx.x >> 5;
    const int wm = (wid >> 3) * 32, wn = (wid & 7) * 16;
    const float* sW = s_w + OFF_G4;
    float* P = g_part4 + (size_t)s * (2 * B_ * FEAT_);
    #pragma unroll
    for (int mt = 0; mt < 2; ++mt) {
        const int r = m0 + wm + mt * 16 + (lane >> 2);
        const float sa0 = sa_hg[r * NSPL4 + s];
        const float sa1 = sa_hg[(r + 8) * NSPL4 + s];
        #pragma unroll
        for (int nt = 0; nt < 2; ++nt) {
            const int c = n0 + wn + nt * 8 + (lane & 3) * 2;
            P[(size_t)r * FEAT_ + c]           = comb(hh[mt][nt][0], xx[mt][nt][0]) * sa0 * sW[c];
            P[(size_t)r * FEAT_ + c + 1]       = comb(hh[mt][nt][1], xx[mt][nt][1]) * sa0 * sW[c + 1];
            P[(size_t)(r + 8) * FEAT_ + c]     = comb(hh[mt][nt][2], xx[mt][nt][2]) * sa1 * sW[c];
            P[(size_t)(r + 8) * FEAT_ + c + 1] = comb(hh[mt][nt][3], xx[mt][nt][3]) * sa1 * sW[c + 1];
        }
    }
}

__global__ void __launch_bounds__(256) k_reduce4(const float* __restrict__ bg4)
{
    const int idx = blockIdx.x * blockDim.x + threadIdx.x;
    if (idx >= 2 * B_ * FEAT_) return;
    const int col = idx & (FEAT_ - 1);
    float v = bg4[col];
    #pragma unroll
    for (int s = 0; s < NSPL4; ++s)
        v += g_part4[(size_t)s * (2 * B_ * FEAT_) + idx];
    g_o[idx] = silu_f(v);
}

__global__ void __launch_bounds__(256) k_dot()
{
    const int b = blockIdx.x, t = threadIdx.x;
    const float* qo = g_o + (size_t)b * FEAT_;
    const float* ko = g_o + (size_t)(B_ + b) * FEAT_;
    float s = 0.0f;
    for (int i = t; i < FEAT_; i += 256) s = fmaf(qo[i], ko[i], s);
    __shared__ float sh[256];
    sh[t] = s; __syncthreads();
    for (int off = 128; off > 0; off >>= 1) {
        if (t < off) sh[t] += sh[t + off];
        __syncthreads();
    }
    if (t == 0) g_scores[b] = sh[0];
}

__global__ void __launch_bounds__(256) k_softmax(float* __restrict__ out)
{
    const int t = threadIdx.x;
    __shared__ float sh[256];
    float v = g_scores[t];
    sh[t] = v; __syncthreads();
    for (int off = 128; off > 0; off >>= 1) {
        if (t < off) sh[t] = fmaxf(sh[t], sh[t + off]);
        __syncthreads();
    }
    const float m = sh[0]; __syncthreads();
    const float e = expf(v - m);
    sh[t] = e; __syncthreads();
    for (int off = 128; off > 0; off >>= 1) {
        if (t < off) sh[t] += sh[t + off];
        __syncthreads();
    }
    out[t] = e / sh[0];
}

// ================= launch =================
extern "C" void kernel_launch(void* const* d_in, const int* in_sizes, int n_in,
                              void* d_out, int out_size)
{
    const float* q   = (const float*)d_in[0];
    const float* k   = (const float*)d_in[1];
    const float* Wq1 = (const float*)d_in[2];
    const float* bq1 = (const float*)d_in[3];
    const float* Wq4 = (const float*)d_in[4];
    const float* bq4 = (const float*)d_in[5];
    const float* Wk1 = (const float*)d_in[6];
    const float* bk1 = (const float*)d_in[7];
    const float* Wk4 = (const float*)d_in[8];
    const float* bk4 = (const float*)d_in[9];
    const float* Wg1 = (const float*)d_in[10];
    const float* bg1 = (const float*)d_in[11];
    const float* Wg4 = (const float*)d_in[12];
    const float* bg4 = (const float*)d_in[13];
    float* out = (float*)d_out;

    cudaFuncSetAttribute(k_fc1g, cudaFuncAttributeMaxDynamicSharedMemorySize, SMEM_TOTAL);
    cudaFuncSetAttribute(k_fc4g, cudaFuncAttributeMaxDynamicSharedMemorySize, SMEM_TOTAL);
    cudaFuncSetAttribute(k_gf1,  cudaFuncAttributeMaxDynamicSharedMemorySize, SMEM_TOTAL);
    cudaFuncSetAttribute(k_gf4,  cudaFuncAttributeMaxDynamicSharedMemorySize, SMEM_TOTAL);

    k_zero_cmax<<<(N_SC + 255) / 256, 256>>>();
    k_colmax<<<dim3(37, 4),  256>>>(Wq1, GS_,       HID_,  G_ * GS_,   OFF_W1Q);
    k_colmax<<<dim3(37, 4),  256>>>(Wk1, GS_,       HID_,  G_ * GS_,   OFF_W1K);
    k_colmax<<<dim3(64, 8),  256>>>(Wq4, HID_,      FEAT_, G_ * HID_,  OFF_W4Q);
    k_colmax<<<dim3(64, 8),  256>>>(Wk4, HID_,      FEAT_, G_ * HID_,  OFF_W4K);
    k_colmax<<<dim3(128, 4), 256>>>(Wg1, G_ * FEAT_, HID_, G_ * FEAT_, OFF_G1);
    k_colmax<<<dim3(4, 8),   256>>>(Wg4, HID_,      FEAT_, HID_,       OFF_G4);
    k_finalize_scales<<<(N_SC + 255) / 256, 256>>>();
    k_quant_qk<<<dim3(G_, B_, 2), 128>>>(q, k);

    k_fc1g<<<dim3(4, 8, 32),      THREADS, SMEM_TOTAL>>>(Wq1, bq1, Wk1, bk1);
    k_quant_h<<<dim3(G_, 2 * B_), 256>>>();
    k_fc4g<<<dim3(4, 16, 32),     THREADS, SMEM_TOTAL>>>(Wq4, bq4, Wk4, bk4);
    k_quant_f<<<dim3(NSPL, 2 * B_), 256>>>();
    k_gf1<<<dim3(8, 8, NSPL),     THREADS, SMEM_TOTAL>>>(Wg1);
    k_reduce_silu_quant<<<dim3(NSPL4, 2 * B_), 128>>>(bg1);
    k_gf4<<<dim3(8, 16, NSPL4),   THREADS, SMEM_TOTAL>>>(Wg4);
    k_reduce4<<<(2 * B_ * FEAT_) / 256, 256>>>(bg4);
    k_dot<<<B_, 256>>>();
    k_softmax<<<1, 256>>>(out);
}

// round 10
// speedup vs baseline: 2.8504x; 2.8504x over previous
#include <cuda_runtime.h>
#include <cuda_fp16.h>
#include <math.h>
#include <stdint.h>

#define B_    256
#define G_    16
#define GS_   588
#define GSP   640
#define HID_  1024
#define FEAT_ 2048
#define NSPL  32
#define KSPL  ((G_ * FEAT_) / NSPL)   // 1024
#define NSPL4 8
#define KSPL4 (HID_ / NSPL4)          // 128

#define THREADS 512
#define BM 128
#define BN 128
#define BK 64
#define BKP 72     // padded A row (halves): 144B stride, conflict-free LDSM
#define BNP 136    // padded B row (halves): 272B stride, conflict-free LDSM

// per-buffer SMEM layout (bytes)
#define PB_AHI 0
#define PB_ALO 18432
#define PB_BHI 36864
#define PB_BLO 54272
#define BUF_BYTES 71680
#define SMEM_TOTAL (2 * BUF_BYTES)   // 143360

// ---------------- scratch (device globals) ----------------
__device__ __half g_qk_hi[(size_t)2 * G_ * B_ * GSP];   // [(br*16+g)*256+b][640]
__device__ __half g_qk_lo[(size_t)2 * G_ * B_ * GSP];
__device__ __half g_h_hi[(size_t)2 * B_ * G_ * HID_];
__device__ __half g_h_lo[(size_t)2 * B_ * G_ * HID_];
__device__ __half g_f_hi[(size_t)2 * B_ * G_ * FEAT_];
__device__ __half g_f_lo[(size_t)2 * B_ * G_ * FEAT_];
__device__ float  g_part[(size_t)NSPL * 2 * B_ * HID_];
__device__ float  g_part4[(size_t)NSPL4 * 2 * B_ * FEAT_];
__device__ __half g_hg_hi[(size_t)2 * B_ * HID_];
__device__ __half g_hg_lo[(size_t)2 * B_ * HID_];
__device__ float  g_o[(size_t)2 * B_ * FEAT_];
__device__ float  g_scores[B_];

__device__ __forceinline__ float silu_f(float v) {
    return v / (1.0f + __expf(-v));
}
__device__ __forceinline__ uint32_t smem_to_u32(const void* p) {
    uint32_t a;
    asm("{ .reg .u64 t; cvta.to.shared.u64 t, %1; cvt.u32.u64 %0, t; }"
        : "=r"(a) : "l"(p));
    return a;
}

// ---- family-portable primitives (valid on compute_103) ----
__device__ __forceinline__ void ldsm_x4(uint32_t* r, uint32_t addr) {
    asm volatile("ldmatrix.sync.aligned.m8n8.x4.shared.b16 {%0,%1,%2,%3}, [%4];"
        : "=r"(r[0]), "=r"(r[1]), "=r"(r[2]), "=r"(r[3]) : "r"(addr));
}
__device__ __forceinline__ void ldsm_x2t(uint32_t* r, uint32_t addr) {
    asm volatile("ldmatrix.sync.aligned.m8n8.x2.trans.shared.b16 {%0,%1}, [%2];"
        : "=r"(r[0]), "=r"(r[1]) : "r"(addr));
}
__device__ __forceinline__ void mma_f32(float* d, const uint32_t* a, const uint32_t* b) {
    asm volatile(
        "mma.sync.aligned.m16n8k16.row.col.f32.f16.f16.f32 "
        "{%0,%1,%2,%3}, {%4,%5,%6,%7}, {%8,%9}, {%0,%1,%2,%3};"
        : "+f"(d[0]), "+f"(d[1]), "+f"(d[2]), "+f"(d[3])
        : "r"(a[0]), "r"(a[1]), "r"(a[2]), "r"(a[3]), "r"(b[0]), "r"(b[1]));
}
__device__ __forceinline__ void mma_f16(uint32_t* d, const uint32_t* a, const uint32_t* b) {
    asm volatile(
        "mma.sync.aligned.m16n8k16.row.col.f16.f16.f16.f16 "
        "{%0,%1}, {%2,%3,%4,%5}, {%6,%7}, {%0,%1};"
        : "+r"(d[0]), "+r"(d[1])
        : "r"(a[0]), "r"(a[1]), "r"(a[2]), "r"(a[3]), "r"(b[0]), "r"(b[1]));
}
__device__ __forceinline__ void cp_async16(uint32_t dst, const void* src) {
    asm volatile("cp.async.ca.shared.global [%0], [%1], 16;" :: "r"(dst), "l"(src));
}
__device__ __forceinline__ void cp_async_commit() {
    asm volatile("cp.async.commit_group;" ::: "memory");
}
__device__ __forceinline__ void cp_async_wait0() {
    asm volatile("cp.async.wait_group 0;" ::: "memory");
}

__device__ __forceinline__ void split_f32(float x, __half& hi, __half& lo) {
    hi = __float2half_rn(x);
    lo = __float2half_rn(x - __half2float(hi));
}
__device__ __forceinline__ void split_store2(__half* hi, __half* lo, float v0, float v1) {
    __half h0, l0, h1, l1;
    split_f32(v0, h0, l0); split_f32(v1, h1, l1);
    *reinterpret_cast<__half2*>(hi) = __halves2half2(h0, h1);
    *reinterpret_cast<__half2*>(lo) = __halves2half2(l0, l1);
}
__device__ __forceinline__ void split4(const float* v, uint32_t* hi2, uint32_t* lo2) {
    __half h0,l0,h1,l1,h2,l2,h3,l3;
    split_f32(v[0], h0, l0); split_f32(v[1], h1, l1);
    split_f32(v[2], h2, l2); split_f32(v[3], h3, l3);
    __half2 a = __halves2half2(h0, h1), b = __halves2half2(h2, h3);
    __half2 c = __halves2half2(l0, l1), d = __halves2half2(l2, l3);
    hi2[0] = *reinterpret_cast<uint32_t*>(&a);
    hi2[1] = *reinterpret_cast<uint32_t*>(&b);
    lo2[0] = *reinterpret_cast<uint32_t*>(&c);
    lo2[1] = *reinterpret_cast<uint32_t*>(&d);
}

// ---------------- GEMM body (512 threads, warp grid 4x4, 32x32/warp, BK=64) ----
// A given as pre-split hi/lo half planes (row stride lda halves, zero-padded past K).
__device__ __forceinline__ void gemm_body(
    const __half* __restrict__ Ah, const __half* __restrict__ Al, int lda,
    const float* __restrict__ W, int ldw,
    int K, int m0, int n0, float acc[2][4][4])
{
    extern __shared__ char dyn[];
    const uint32_t sb = smem_to_u32(dyn);

    const int tid  = threadIdx.x;
    const int lane = tid & 31;
    const int wid  = tid >> 5;
    const int wm   = (wid >> 2) * 32;
    const int wn   = (wid & 3) * 32;

    const int ar = tid >> 2;
    const int as = (tid & 3) << 4;
    const int kr = tid >> 3;
    const int nb = (tid & 7) << 4;

    const int nk = (K + BK - 1) / BK;

    uint32_t accc[2][4][2];
    #pragma unroll
    for (int mt = 0; mt < 2; ++mt)
        #pragma unroll
        for (int nt = 0; nt < 4; ++nt) {
            accc[mt][nt][0] = 0u; accc[mt][nt][1] = 0u;
            #pragma unroll
            for (int e = 0; e < 4; ++e) acc[mt][nt][e] = 0.0f;
        }

    float rb[16];

    auto cpA = [&](int k0, int buf) {
        const uint32_t d = sb + buf * BUF_BYTES + (uint32_t)(ar * BKP + as) * 2;
        const size_t go = (size_t)(m0 + ar) * lda + k0 + as;
        cp_async16(d + PB_AHI,      Ah + go);
        cp_async16(d + PB_AHI + 16, Ah + go + 8);
        cp_async16(d + PB_ALO,      Al + go);
        cp_async16(d + PB_ALO + 16, Al + go + 8);
    };
    auto ldgB = [&](int k0) {
        const int kgB = k0 + kr;
        if (kgB < K) {
            const float* Wp = W + (size_t)kgB * ldw + n0 + nb;
            #pragma unroll
            for (int i = 0; i < 4; ++i) {
                float4 v = *reinterpret_cast<const float4*>(Wp + i * 4);
                rb[i*4+0] = v.x; rb[i*4+1] = v.y; rb[i*4+2] = v.z; rb[i*4+3] = v.w;
            }
        } else {
            #pragma unroll
            for (int i = 0; i < 16; ++i) rb[i] = 0.0f;
        }
    };
    auto stB = [&](int buf) {
        char* base = dyn + buf * BUF_BYTES;
        uint32_t hi2[4], lo2[4];
        split4(rb,     hi2,     lo2);
        split4(rb + 4, hi2 + 2, lo2 + 2);
        *reinterpret_cast<uint4*>(base + PB_BHI + (kr*BNP + nb)*2) =
            make_uint4(hi2[0], hi2[1], hi2[2], hi2[3]);
        *reinterpret_cast<uint4*>(base + PB_BLO + (kr*BNP + nb)*2) =
            make_uint4(lo2[0], lo2[1], lo2[2], lo2[3]);
        split4(rb + 8,  hi2,     lo2);
        split4(rb + 12, hi2 + 2, lo2 + 2);
        *reinterpret_cast<uint4*>(base + PB_BHI + (kr*BNP + nb + 8)*2) =
            make_uint4(hi2[0], hi2[1], hi2[2], hi2[3]);
        *reinterpret_cast<uint4*>(base + PB_BLO + (kr*BNP + nb + 8)*2) =
            make_uint4(lo2[0], lo2[1], lo2[2], lo2[3]);
    };

    // prologue
    cpA(0, 0);
    ldgB(0);
    stB(0);
    cp_async_commit();
    cp_async_wait0();
    __syncthreads();

    for (int t = 0; t < nk; ++t) {
        const int cur = t & 1, nxt = (t + 1) & 1;
        const bool more = (t + 1) < nk;
        const int k0 = t * BK;

        if (more) {
            cpA((t + 1) * BK, nxt);
            cp_async_commit();
            ldgB((t + 1) * BK);
        }

        {
            const uint32_t aHiB = sb + cur * BUF_BYTES + PB_AHI;
            const uint32_t aLoB = sb + cur * BUF_BYTES + PB_ALO;
            const uint32_t bHiB = sb + cur * BUF_BYTES + PB_BHI;
            const uint32_t bLoB = sb + cur * BUF_BYTES + PB_BLO;
            const int l = lane & 15;
            // skip k16-steps entirely past K (fc1g tail: K=588)
            const int ks_end = min(4, (K - k0 + 15) >> 4);
            #pragma unroll
            for (int ks = 0; ks < 4; ++ks) {
                if (ks >= ks_end) break;
                uint32_t bh[4][2], bl[4][2];
                #pragma unroll
                for (int nt = 0; nt < 4; ++nt) {
                    const uint32_t off =
                        ((uint32_t)(ks * 16 + l) * BNP + wn + nt * 8) * 2;
                    ldsm_x2t(bh[nt], bHiB + off);
                    ldsm_x2t(bl[nt], bLoB + off);
                }
                uint32_t ah[2][4], al[2][4];
                #pragma unroll
                for (int mt = 0; mt < 2; ++mt) {
                    const uint32_t offa =
                        ((uint32_t)(wm + mt * 16 + l) * BKP + ks * 16 + (lane >> 4) * 8) * 2;
                    ldsm_x4(ah[mt], aHiB + offa);
                    ldsm_x4(al[mt], aLoB + offa);
                }
                #pragma unroll
                for (int mt = 0; mt < 2; ++mt)
                    #pragma unroll
                    for (int nt = 0; nt < 4; ++nt)
                        mma_f32(acc[mt][nt], ah[mt], bh[nt]);
                #pragma unroll
                for (int mt = 0; mt < 2; ++mt)
                    #pragma unroll
                    for (int nt = 0; nt < 4; ++nt)
                        mma_f16(accc[mt][nt], ah[mt], bl[nt]);
                #pragma unroll
                for (int mt = 0; mt < 2; ++mt)
                    #pragma unroll
                    for (int nt = 0; nt < 4; ++nt)
                        mma_f16(accc[mt][nt], al[mt], bh[nt]);
            }
        }

        if (more) {
            stB(nxt);
            cp_async_wait0();
        }
        __syncthreads();
    }

    #pragma unroll
    for (int mt = 0; mt < 2; ++mt)
        #pragma unroll
        for (int nt = 0; nt < 4; ++nt) {
            const __half2 c01 = *reinterpret_cast<const __half2*>(&accc[mt][nt][0]);
            const __half2 c23 = *reinterpret_cast<const __half2*>(&accc[mt][nt][1]);
            acc[mt][nt][0] += __low2float(c01);
            acc[mt][nt][1] += __high2float(c01);
            acc[mt][nt][2] += __low2float(c23);
            acc[mt][nt][3] += __high2float(c23);
        }
}

// ================= pre-pass: split q,k into padded hi/lo planes =================
// grid (G_, B_, 2); 128 threads
__global__ void __launch_bounds__(128) k_split_qk(
    const float* __restrict__ q, const float* __restrict__ k)
{
    const int g = blockIdx.x, b = blockIdx.y, br = blockIdx.z;
    const int tid = threadIdx.x;
    const float* src = (br ? k : q) + (size_t)b * (G_ * GS_) + g * GS_;
    const size_t base = ((size_t)(br * G_ + g) * B_ + b) * GSP;
    for (int i = tid; i < GSP; i += 128) {
        const float x = (i < GS_) ? src[i] : 0.0f;
        __half h, l;
        split_f32(x, h, l);
        g_qk_hi[base + i] = h;
        g_qk_lo[base + i] = l;
    }
}

// ================= stage kernels =================

// stage 1: grouped fc1 (A pre-split planes). grid (2, 8, 32)
__global__ void __launch_bounds__(THREADS, 1) k_fc1g(
    const float* __restrict__ Wq1, const float* __restrict__ bq1,
    const float* __restrict__ Wk1, const float* __restrict__ bk1)
{
    const int z = blockIdx.z, br = z >> 4, g = z & 15;
    const int m0 = blockIdx.x * BM, n0 = blockIdx.y * BN;

    const size_t abase = (size_t)(br * G_ + g) * B_ * GSP;
    const float* W    = (br ? Wk1 : Wq1) + (size_t)g * GS_ * HID_;
    const float* bias = (br ? bk1 : bq1) + g * HID_;

    float acc[2][4][4];
    gemm_body(g_qk_hi + abase, g_qk_lo + abase, GSP, W, HID_, GS_, m0, n0, acc);

    const int lane = threadIdx.x & 31, wid = threadIdx.x >> 5;
    const int wm = (wid >> 2) * 32, wn = (wid & 3) * 32;
    #pragma unroll
    for (int mt = 0; mt < 2; ++mt) {
        const int r = m0 + wm + mt * 16 + (lane >> 2);
        #pragma unroll
        for (int nt = 0; nt < 4; ++nt) {
            const int c = n0 + wn + nt * 8 + (lane & 3) * 2;
            const float b0 = bias[c], b1 = bias[c + 1];
            const size_t i0 = (size_t)(br * B_ + r) * (G_ * HID_) + (size_t)g * HID_ + c;
            const size_t i1 = i0 + (size_t)8 * (G_ * HID_);
            split_store2(&g_h_hi[i0], &g_h_lo[i0],
                         silu_f(acc[mt][nt][0] + b0), silu_f(acc[mt][nt][1] + b1));
            split_store2(&g_h_hi[i1], &g_h_lo[i1],
                         silu_f(acc[mt][nt][2] + b0), silu_f(acc[mt][nt][3] + b1));
        }
    }
}

// stage 2: grouped fc4 + feature-major interleave. grid (2, 16, 32)
__global__ void __launch_bounds__(THREADS, 1) k_fc4g(
    const float* __restrict__ Wq4, const float* __restrict__ bq4,
    const float* __restrict__ Wk4, const float* __restrict__ bk4)
{
    const int z = blockIdx.z, br = z >> 4, g = z & 15;
    const int m0 = blockIdx.x * BM, n0 = blockIdx.y * BN;

    const __half* Ah  = g_h_hi + (size_t)br * B_ * G_ * HID_ + (size_t)g * HID_;
    const __half* Al  = g_h_lo + (size_t)br * B_ * G_ * HID_ + (size_t)g * HID_;
    const float* W    = (br ? Wk4 : Wq4) + (size_t)g * HID_ * FEAT_;
    const float* bias = (br ? bk4 : bq4) + g * FEAT_;

    float acc[2][4][4];
    gemm_body(Ah, Al, G_ * HID_, W, FEAT_, HID_, m0, n0, acc);

    const int lane = threadIdx.x & 31, wid = threadIdx.x >> 5;
    const int wm = (wid >> 2) * 32, wn = (wid & 3) * 32;
    #pragma unroll
    for (int mt = 0; mt < 2; ++mt) {
        const int r = m0 + wm + mt * 16 + (lane >> 2);
        const size_t rb0 = (size_t)(br * B_ + r)     * (G_ * FEAT_) + g;
        const size_t rb1 = (size_t)(br * B_ + r + 8) * (G_ * FEAT_) + g;
        #pragma unroll
        for (int nt = 0; nt < 4; ++nt) {
            const int c = n0 + wn + nt * 8 + (lane & 3) * 2;
            const float b0 = bias[c], b1 = bias[c + 1];
            const float v0 = silu_f(acc[mt][nt][0] + b0);
            const float v1 = silu_f(acc[mt][nt][1] + b1);
            const float v2 = silu_f(acc[mt][nt][2] + b0);
            const float v3 = silu_f(acc[mt][nt][3] + b1);
            __half h, l;
            split_f32(v0, h, l); g_f_hi[rb0 + (size_t)c * G_] = h;       g_f_lo[rb0 + (size_t)c * G_] = l;
            split_f32(v1, h, l); g_f_hi[rb0 + (size_t)(c + 1) * G_] = h; g_f_lo[rb0 + (size_t)(c + 1) * G_] = l;
            split_f32(v2, h, l); g_f_hi[rb1 + (size_t)c * G_] = h;       g_f_lo[rb1 + (size_t)c * G_] = l;
            split_f32(v3, h, l); g_f_hi[rb1 + (size_t)(c + 1) * G_] = h; g_f_lo[rb1 + (size_t)(c + 1) * G_] = l;
        }
    }
}

// stage 3: global fc1 split-K. grid (4, 8, NSPL=32)
__global__ void __launch_bounds__(THREADS, 1) k_gf1(const float* __restrict__ Wg1)
{
    const int s = blockIdx.z;
    const int m0 = blockIdx.x * BM, n0 = blockIdx.y * BN;

    const __half* Ah = g_f_hi + (size_t)s * KSPL;
    const __half* Al = g_f_lo + (size_t)s * KSPL;
    const float*  W  = Wg1 + (size_t)s * KSPL * HID_;

    float acc[2][4][4];
    gemm_body(Ah, Al, G_ * FEAT_, W, HID_, KSPL, m0, n0, acc);

    const int lane = threadIdx.x & 31, wid = threadIdx.x >> 5;
    const int wm = (wid >> 2) * 32, wn = (wid & 3) * 32;
    float* P = g_part + (size_t)s * (2 * B_ * HID_);
    #pragma unroll
    for (int mt = 0; mt < 2; ++mt) {
        const int r = m0 + wm + mt * 16 + (lane >> 2);
        #pragma unroll
        for (int nt = 0; nt < 4; ++nt) {
            const int c = n0 + wn + nt * 8 + (lane & 3) * 2;
            P[(size_t)r * HID_ + c]           = acc[mt][nt][0];
            P[(size_t)r * HID_ + c + 1]       = acc[mt][nt][1];
            P[(size_t)(r + 8) * HID_ + c]     = acc[mt][nt][2];
            P[(size_t)(r + 8) * HID_ + c + 1] = acc[mt][nt][3];
        }
    }
}

// reduce NSPL partials + bias + silu -> pre-split g_hg
__global__ void __launch_bounds__(256) k_reduce_silu(const float* __restrict__ bg1)
{
    const int idx = blockIdx.x * blockDim.x + threadIdx.x;
    if (idx >= 2 * B_ * HID_) return;
    const int col = idx & (HID_ - 1);
    float v = bg1[col];
    #pragma unroll
    for (int s = 0; s < NSPL; ++s)
        v += g_part[(size_t)s * (2 * B_ * HID_) + idx];
    v = silu_f(v);
    __half h, l;
    split_f32(v, h, l);
    g_hg_hi[idx] = h;
    g_hg_lo[idx] = l;
}

// stage 4: global fc4 split-K. grid (4, 16, NSPL4=8)
__global__ void __launch_bounds__(THREADS, 1) k_gf4(const float* __restrict__ Wg4)
{
    const int s = blockIdx.z;
    const int m0 = blockIdx.x * BM, n0 = blockIdx.y * BN;

    const __half* Ah = g_hg_hi + (size_t)s * KSPL4;
    const __half* Al = g_hg_lo + (size_t)s * KSPL4;
    const float*  W  = Wg4 + (size_t)s * KSPL4 * FEAT_;

    float acc[2][4][4];
    gemm_body(Ah, Al, HID_, W, FEAT_, KSPL4, m0, n0, acc);

    const int lane = threadIdx.x & 31, wid = threadIdx.x >> 5;
    const int wm = (wid >> 2) * 32, wn = (wid & 3) * 32;
    float* P = g_part4 + (size_t)s * (2 * B_ * FEAT_);
    #pragma unroll
    for (int mt = 0; mt < 2; ++mt) {
        const int r = m0 + wm + mt * 16 + (lane >> 2);
        #pragma unroll
        for (int nt = 0; nt < 4; ++nt) {
            const int c = n0 + wn + nt * 8 + (lane & 3) * 2;
            P[(size_t)r * FEAT_ + c]           = acc[mt][nt][0];
            P[(size_t)r * FEAT_ + c + 1]       = acc[mt][nt][1];
            P[(size_t)(r + 8) * FEAT_ + c]     = acc[mt][nt][2];
            P[(size_t)(r + 8) * FEAT_ + c + 1] = acc[mt][nt][3];
        }
    }
}

// reduce NSPL4 partials + bias + silu -> g_o
__global__ void __launch_bounds__(256) k_reduce4(const float* __restrict__ bg4)
{
    const int idx = blockIdx.x * blockDim.x + threadIdx.x;
    if (idx >= 2 * B_ * FEAT_) return;
    const int col = idx & (FEAT_ - 1);
    float v = bg4[col];
    #pragma unroll
    for (int s = 0; s < NSPL4; ++s)
        v += g_part4[(size_t)s * (2 * B_ * FEAT_) + idx];
    g_o[idx] = silu_f(v);
}

// stage 5: per-batch dot
__global__ void __launch_bounds__(256) k_dot()
{
    const int b = blockIdx.x, t = threadIdx.x;
    const float* qo = g_o + (size_t)b * FEAT_;
    const float* ko = g_o + (size_t)(B_ + b) * FEAT_;
    float s = 0.0f;
    for (int i = t; i < FEAT_; i += 256)
        s = fmaf(qo[i], ko[i], s);
    __shared__ float sh[256];
    sh[t] = s;
    __syncthreads();
    for (int off = 128; off > 0; off >>= 1) {
        if (t < off) sh[t] += sh[t + off];
        __syncthreads();
    }
    if (t == 0) g_scores[b] = sh[0];
}

// stage 6: softmax over batch
__global__ void __launch_bounds__(256) k_softmax(float* __restrict__ out)
{
    const int t = threadIdx.x;
    __shared__ float sh[256];
    float v = g_scores[t];
    sh[t] = v;
    __syncthreads();
    for (int off = 128; off > 0; off >>= 1) {
        if (t < off) sh[t] = fmaxf(sh[t], sh[t + off]);
        __syncthreads();
    }
    const float m = sh[0];
    __syncthreads();
    const float e = expf(v - m);
    sh[t] = e;
    __syncthreads();
    for (int off = 128; off > 0; off >>= 1) {
        if (t < off) sh[t] += sh[t + off];
        __syncthreads();
    }
    out[t] = e / sh[0];
}

// ================= launch =================
extern "C" void kernel_launch(void* const* d_in, const int* in_sizes, int n_in,
                              void* d_out, int out_size)
{
    const float* q   = (const float*)d_in[0];
    const float* k   = (const float*)d_in[1];
    const float* Wq1 = (const float*)d_in[2];
    const float* bq1 = (const float*)d_in[3];
    const float* Wq4 = (const float*)d_in[4];
    const float* bq4 = (const float*)d_in[5];
    const float* Wk1 = (const float*)d_in[6];
    const float* bk1 = (const float*)d_in[7];
    const float* Wk4 = (const float*)d_in[8];
    const float* bk4 = (const float*)d_in[9];
    const float* Wg1 = (const float*)d_in[10];
    const float* bg1 = (const float*)d_in[11];
    const float* Wg4 = (const float*)d_in[12];
    const float* bg4 = (const float*)d_in[13];
    float* out = (float*)d_out;

    cudaFuncSetAttribute(k_fc1g, cudaFuncAttributeMaxDynamicSharedMemorySize, SMEM_TOTAL);
    cudaFuncSetAttribute(k_fc4g, cudaFuncAttributeMaxDynamicSharedMemorySize, SMEM_TOTAL);
    cudaFuncSetAttribute(k_gf1,  cudaFuncAttributeMaxDynamicSharedMemorySize, SMEM_TOTAL);
    cudaFuncSetAttribute(k_gf4,  cudaFuncAttributeMaxDynamicSharedMemorySize, SMEM_TOTAL);

    k_split_qk<<<dim3(G_, B_, 2), 128>>>(q, k);
    k_fc1g<<<dim3(2, 8, 2 * G_),   THREADS, SMEM_TOTAL>>>(Wq1, bq1, Wk1, bk1);
    k_fc4g<<<dim3(2, 16, 2 * G_),  THREADS, SMEM_TOTAL>>>(Wq4, bq4, Wk4, bk4);
    k_gf1<<<dim3(4, 8, NSPL),      THREADS, SMEM_TOTAL>>>(Wg1);
    k_reduce_silu<<<(2 * B_ * HID_) / 256, 256>>>(bg1);
    k_gf4<<<dim3(4, 16, NSPL4),    THREADS, SMEM_TOTAL>>>(Wg4);
    k_reduce4<<<(2 * B_ * FEAT_) / 256, 256>>>(bg4);
    k_dot<<<B_, 256>>>();
    k_softmax<<<1, 256>>>(out);
}